// round 13
// baseline (speedup 1.0000x reference)
#include <cuda_runtime.h>
#include <cuda_fp16.h>
#include <cstdint>
#include <math.h>

#define S_LEN 4096
#define BATCH 2
#define DM    768
#define DFF   3072
#define NH    12
#define DK    64
#define NTOK  (BATCH * S_LEN)
#define QS    2304            // fused qkv row stride

// ---------------- scratch (device globals: no allocation allowed) ----------
__device__ __half g_h   [NTOK * DM];
__device__ __half g_qkv [NTOK * QS];
__device__ __half g_ctx [NTOK * DM];
__device__ float  g_x2  [NTOK * DM];
__device__ __half g_ff  [NTOK * DFF];
__device__ float  g_bqkv[QS];
// weight fragments (u32 = f16x2), layout [ntile][ktile][2048]
__device__ uint32_t g_wqkvf[3 * DM * DM / 2];
__device__ uint32_t g_wof  [DM * DM / 2];
__device__ uint32_t g_w1f  [DFF * DM / 2];
__device__ uint32_t g_w2f  [DM * DFF / 2];

// ---------------- helpers --------------------------------------------------
__device__ __forceinline__ uint32_t pack_h2(float lo, float hi) {
    uint32_t r; asm("cvt.rn.f16x2.f32 %0, %1, %2;" : "=r"(r) : "f"(hi), "f"(lo)); return r;
}
__device__ __forceinline__ float fexp2(float x) {
    float r; asm("ex2.approx.f32 %0, %1;" : "=f"(r) : "f"(x)); return r;
}

__device__ __forceinline__ void mma_f16(float c[4], const uint4& a, const uint2& b) {
    asm volatile(
        "mma.sync.aligned.m16n8k16.row.col.f32.f16.f16.f32 "
        "{%0,%1,%2,%3}, {%4,%5,%6,%7}, {%8,%9}, {%0,%1,%2,%3};"
        : "+f"(c[0]), "+f"(c[1]), "+f"(c[2]), "+f"(c[3])
        : "r"(a.x), "r"(a.y), "r"(a.z), "r"(a.w), "r"(b.x), "r"(b.y));
}

#define CP16(dst, src) \
    asm volatile("cp.async.ca.shared.global [%0], [%1], 16;" :: "r"(dst), "l"(src))
#define CP_COMMIT() asm volatile("cp.async.commit_group;" ::: "memory")
#define CP_WAIT(N)  asm volatile("cp.async.wait_group %0;" :: "n"(N) : "memory")

__device__ __forceinline__ void ldm_x4(uint4& r, uint32_t a) {
    asm volatile("ldmatrix.sync.aligned.m8n8.x4.shared.b16 {%0,%1,%2,%3}, [%4];"
        : "=r"(r.x), "=r"(r.y), "=r"(r.z), "=r"(r.w) : "r"(a));
}
__device__ __forceinline__ void ldm_x4t(uint4& r, uint32_t a) {
    asm volatile("ldmatrix.sync.aligned.m8n8.x4.trans.shared.b16 {%0,%1,%2,%3}, [%4];"
        : "=r"(r.x), "=r"(r.y), "=r"(r.z), "=r"(r.w) : "r"(a));
}

// ---------------- weight prep: f32 [N][K] -> B-fragment half layout --------
__global__ void prep_w(const float* __restrict__ W, uint32_t* __restrict__ out, int K) {
    const int idx = blockIdx.x * 256 + threadIdx.x;
    const int tile = idx >> 11, j = idx & 2047;
    const int ktiles = K >> 5;
    const int ntile = tile / ktiles, ktile = tile - ntile * ktiles;
    const int reg = j & 1, lane = (j >> 1) & 31, nt = (j >> 6) & 15, kt = j >> 10;
    const int n = ntile * 128 + nt * 8 + (lane >> 2);
    const int k = ktile * 32 + kt * 16 + (lane & 3) * 2 + 8 * reg;
    out[idx] = pack_h2(W[(size_t)n * K + k], W[(size_t)n * K + k + 1]);
}

__global__ void cat_bias(const float* __restrict__ a, const float* __restrict__ b,
                         const float* __restrict__ c, float* __restrict__ o) {
    const int i = blockIdx.x * 256 + threadIdx.x;
    if (i < QS)
        o[i] = i < 768 ? a[i] : (i < 1536 ? b[i - 768] : c[i - 1536]);
}

// ---------------- layernorm-ish (scalar alpha/beta, ddof=1 std) -----------
__global__ void norm_kernel(const float* __restrict__ x, __half* __restrict__ out,
                            const float* __restrict__ alpha, const float* __restrict__ beta) {
    const int row = blockIdx.x;
    const float* xr = x + (size_t)row * DM;
    __half* orow = out + (size_t)row * DM;

    float v0 = xr[threadIdx.x];
    float v1 = xr[threadIdx.x + 256];
    float v2 = xr[threadIdx.x + 512];
    float s  = v0 + v1 + v2;
    float sq = v0 * v0 + v1 * v1 + v2 * v2;

    __shared__ float red0[8], red1[8];
    __shared__ float s_mean, s_scale, s_beta;
    #pragma unroll
    for (int o = 16; o > 0; o >>= 1) {
        s  += __shfl_xor_sync(0xffffffffu, s,  o);
        sq += __shfl_xor_sync(0xffffffffu, sq, o);
    }
    const int warp = threadIdx.x >> 5, lane = threadIdx.x & 31;
    if (lane == 0) { red0[warp] = s; red1[warp] = sq; }
    __syncthreads();
    if (threadIdx.x == 0) {
        float S = 0.f, SQ = 0.f;
        #pragma unroll
        for (int i = 0; i < 8; i++) { S += red0[i]; SQ += red1[i]; }
        const float mean = S / (float)DM;
        float var = (SQ - (float)DM * mean * mean) / (float)(DM - 1);
        var = fmaxf(var, 0.f);
        s_mean  = mean;
        s_scale = alpha[0] / (sqrtf(var) + 1e-6f);
        s_beta  = beta[0];
    }
    __syncthreads();
    const float mean = s_mean, scale = s_scale, bb = s_beta;
    orow[threadIdx.x]       = __float2half_rn((v0 - mean) * scale + bb);
    orow[threadIdx.x + 256] = __float2half_rn((v1 - mean) * scale + bb);
    orow[threadIdx.x + 512] = __float2half_rn((v2 - mean) * scale + bb);
}

// =================== fp16 GEMM: cp.async + ldmatrix A, pre-fragged B =======
// C = A[M,K] @ W[N,K]^T (+bias).  MODE 0: half out. 1: half+relu. 2: f32+res.
// MT = m16-tiles per warp (4 -> 128-row CTA, 2 -> 64-row CTA).
// 3-stage ring, distance-1 prefetch, 1 sync/iter.
#define G_STG(MT)   ((MT) * 32 * 80 + 8192)
#define G_DSMEM(MT) (3 * G_STG(MT))

template <int MODE, int MT>
__global__ void __launch_bounds__(256, 2)
gemm_mma(const __half* __restrict__ A, const uint32_t* __restrict__ Wf,
         const float* __restrict__ bias, const float* __restrict__ res,
         void* __restrict__ Cv, int M, int N, int K) {
    extern __shared__ char smc[];
    const uint32_t sb = (uint32_t)__cvta_generic_to_shared(smc);
    constexpr int STG = G_STG(MT);
    constexpr int ABYTES = MT * 32 * 80;

    const int t    = threadIdx.x;
    const int lane = t & 31;
    const int wid  = t >> 5;
    const int wy   = wid >> 2;
    const int wx   = wid & 3;
    const int bm   = blockIdx.y * (MT * 32);
    const int bn   = blockIdx.x * 128;

    const __half* Ab = A + (size_t)bm * K;
    const uint32_t* Wtile0 = Wf + (size_t)(bn >> 7) * (K >> 5) * 2048;

    float acc[MT][4][4];
    #pragma unroll
    for (int i = 0; i < MT; i++)
        #pragma unroll
        for (int j = 0; j < 4; j++)
            #pragma unroll
            for (int r = 0; r < 4; r++) acc[i][j][r] = 0.f;

    const int arowp = t >> 2, achp = t & 3;

    auto stage = [&](int ktile, int s) {
        const uint32_t ab = sb + s * STG;
        #pragma unroll
        for (int p = 0; p < MT / 2; p++) {
            const int row = arowp + p * 64;
            CP16(ab + row * 80 + achp * 16,
                 (const char*)(Ab + (size_t)row * K + ktile * 32) + achp * 16);
        }
        const uint32_t bb = ab + ABYTES;
        const char* wsrc = (const char*)(Wtile0 + (size_t)ktile * 2048);
        CP16(bb + t * 16,         wsrc + t * 16);
        CP16(bb + (t + 256) * 16, wsrc + (t + 256) * 16);
    };

    const int army = ((lane >> 3) & 1) * 8 + (lane & 7);
    const int acol = ((lane >> 4) & 1) * 8;

    auto compute = [&](int s) {
        const uint32_t ab = sb + s * STG;
        const uint32_t* Bs = (const uint32_t*)(smc + s * STG + ABYTES);
        #pragma unroll
        for (int kt = 0; kt < 2; kt++) {
            uint4 af[MT];
            #pragma unroll
            for (int mt = 0; mt < MT; mt++)
                ldm_x4(af[mt], ab + (uint32_t)((wy * (MT * 16) + mt * 16 + army) * 80
                                               + (kt * 16 + acol) * 2));
            uint2 bf[4];
            #pragma unroll
            for (int nt = 0; nt < 4; nt++)
                bf[nt] = *(const uint2*)&Bs[((kt * 16 + wx * 4 + nt) * 32 + lane) * 2];
            #pragma unroll
            for (int mt = 0; mt < MT; mt++)
                #pragma unroll
                for (int nt = 0; nt < 4; nt++)
                    mma_f16(acc[mt][nt], af[mt], bf[nt]);
        }
    };

    const int niter = K / 32;

    stage(0, 0);
    CP_COMMIT();
    for (int i = 0; i < niter; i++) {
        if (i + 1 < niter) {
            stage(i + 1, (i + 1) % 3);
            CP_COMMIT();
            CP_WAIT(1);
        } else {
            CP_WAIT(0);
        }
        __syncthreads();
        compute(i % 3);
    }

    const int rbase = bm + wy * (MT * 16) + (lane >> 2);
    const int cbase = bn + wx * 32 + (lane & 3) * 2;
    #pragma unroll
    for (int mt = 0; mt < MT; mt++) {
        #pragma unroll
        for (int nt = 0; nt < 4; nt++) {
            const int c = cbase + nt * 8;
            const float b0 = bias[c], b1 = bias[c + 1];
            const int r0 = rbase + mt * 16;
            const int r1 = r0 + 8;
            float v0 = acc[mt][nt][0] + b0;
            float v1 = acc[mt][nt][1] + b1;
            float v2 = acc[mt][nt][2] + b0;
            float v3 = acc[mt][nt][3] + b1;
            if (MODE == 1) {
                v0 = fmaxf(v0, 0.f); v1 = fmaxf(v1, 0.f);
                v2 = fmaxf(v2, 0.f); v3 = fmaxf(v3, 0.f);
            }
            if (MODE == 2) {
                const float2 q0 = *(const float2*)&res[(size_t)r0 * N + c];
                const float2 q1 = *(const float2*)&res[(size_t)r1 * N + c];
                float* C = (float*)Cv;
                *(float2*)&C[(size_t)r0 * N + c] = make_float2(v0 + q0.x, v1 + q0.y);
                *(float2*)&C[(size_t)r1 * N + c] = make_float2(v2 + q1.x, v3 + q1.y);
            } else {
                __half* C = (__half*)Cv;
                *(uint32_t*)&C[(size_t)r0 * N + c] = pack_h2(v0, v1);
                *(uint32_t*)&C[(size_t)r1 * N + c] = pack_h2(v2, v3);
            }
        }
    }
}

// =================== fp16 flash attention: cp.async + ldmatrix =============
// Reads fused qkv [NTOK][2304] (Q at col 0, K at 768, V at 1536).
// CTA: 128 queries (one (b,h)); 8 warps x 16 queries; BN=64 keys/iter.
// 3-stage ring, 1 sync/iter, register-resident P, log2-domain softmax.
#define A_STG   18688                 // K 9216 + V 9216 + mask 256
#define A_DSMEM (3 * A_STG)
#define SCL2    0.1803368801f         // 0.125 * log2(e)

__global__ void __launch_bounds__(256, 2)
attn_mma(const __half* __restrict__ qkv, const int* __restrict__ mask,
         __half* __restrict__ Oh) {
    extern __shared__ char smc[];
    const uint32_t sb = (uint32_t)__cvta_generic_to_shared(smc);

    const int t = threadIdx.x, lane = t & 31, wid = t >> 5;
    const int q0 = blockIdx.x * 128;
    const int h  = blockIdx.y, b = blockIdx.z;
    const __half* Qb = qkv + (size_t)b * S_LEN * QS + h * DK;
    const __half* Kb = Qb + 768;
    const __half* Vb = Qb + 1536;
    const size_t obase = (size_t)b * S_LEN * DM + (size_t)h * DK;

    // ---- persistent Q A-fragments (16 queries per warp) ----
    const int qrow = q0 + wid * 16 + (lane >> 2);
    uint4 aq[4];
    #pragma unroll
    for (int kt = 0; kt < 4; kt++) {
        const __half* qp = Qb + (size_t)qrow * QS + kt * 16 + (lane & 3) * 2;
        aq[kt].x = *(const uint32_t*)qp;
        aq[kt].y = *(const uint32_t*)(qp + (size_t)8 * QS);
        aq[kt].z = *(const uint32_t*)(qp + 8);
        aq[kt].w = *(const uint32_t*)(qp + (size_t)8 * QS + 8);
    }

    float m0 = -INFINITY, m1 = -INFINITY, l0 = 0.f, l1 = 0.f;
    float o[8][4];
    #pragma unroll
    for (int i = 0; i < 8; i++)
        #pragma unroll
        for (int j = 0; j < 4; j++) o[i][j] = 0.f;

    const int srow = t >> 3, sch = t & 7;

    auto stage = [&](int ks0, int s) {
        const uint32_t kb = sb + s * A_STG;
        #pragma unroll
        for (int p = 0; p < 2; p++) {
            const int row = srow + p * 32;
            CP16(kb + row * 144 + sch * 16,
                 (const char*)(Kb + (size_t)(ks0 + row) * QS) + sch * 16);
            CP16(kb + 9216 + row * 144 + sch * 16,
                 (const char*)(Vb + (size_t)(ks0 + row) * QS) + sch * 16);
        }
        if (t < 16)
            CP16(kb + 18432 + t * 16, (const char*)(mask + (size_t)b * S_LEN + ks0) + t * 16);
    };

    const int krow = ((lane >> 4) & 1) * 8 + (lane & 7);
    const int kcol = ((lane >> 3) & 1) * 8;
    const int vrow = ((lane >> 3) & 1) * 8 + (lane & 7);
    const int vcol = ((lane >> 4) & 1) * 8;

    stage(0, 0);
    CP_COMMIT();

    for (int i = 0; i < 64; i++) {
        if (i + 1 < 64) {
            stage((i + 1) * 64, (i + 1) % 3);
            CP_COMMIT();
            CP_WAIT(1);
        } else {
            CP_WAIT(0);
        }
        __syncthreads();
        const int s = i % 3;
        const uint32_t kb = sb + s * A_STG;
        const uint32_t vb = kb + 9216;
        const int* mk = (const int*)(smc + s * A_STG + 18432);

        // ---- S = Q K^T ----
        float sc[8][4];
        #pragma unroll
        for (int nt = 0; nt < 8; nt++)
            #pragma unroll
            for (int r = 0; r < 4; r++) sc[nt][r] = 0.f;
        #pragma unroll
        for (int kt = 0; kt < 4; kt++) {
            uint2 bf[8];
            #pragma unroll
            for (int kg = 0; kg < 4; kg++) {
                uint4 r4;
                ldm_x4(r4, kb + (uint32_t)((kg * 16 + krow) * 144 + (kt * 16 + kcol) * 2));
                bf[2 * kg]     = make_uint2(r4.x, r4.y);
                bf[2 * kg + 1] = make_uint2(r4.z, r4.w);
            }
            #pragma unroll
            for (int nt = 0; nt < 8; nt++)
                mma_f16(sc[nt], aq[kt], bf[nt]);
        }

        // ---- mask + log2-scale + in-register row max ----
        float mx0 = -INFINITY, mx1 = -INFINITY;
        #pragma unroll
        for (int nt = 0; nt < 8; nt++) {
            const int c = nt * 8 + (lane & 3) * 2;
            const int2 mm = *(const int2*)&mk[c];
            const bool ma = mm.x != 0, mb = mm.y != 0;
            sc[nt][0] = ma ? sc[nt][0] * SCL2 : -1e9f;
            sc[nt][1] = mb ? sc[nt][1] * SCL2 : -1e9f;
            sc[nt][2] = ma ? sc[nt][2] * SCL2 : -1e9f;
            sc[nt][3] = mb ? sc[nt][3] * SCL2 : -1e9f;
            mx0 = fmaxf(mx0, fmaxf(sc[nt][0], sc[nt][1]));
            mx1 = fmaxf(mx1, fmaxf(sc[nt][2], sc[nt][3]));
        }
        mx0 = fmaxf(mx0, __shfl_xor_sync(0xffffffffu, mx0, 1));
        mx0 = fmaxf(mx0, __shfl_xor_sync(0xffffffffu, mx0, 2));
        mx1 = fmaxf(mx1, __shfl_xor_sync(0xffffffffu, mx1, 1));
        mx1 = fmaxf(mx1, __shfl_xor_sync(0xffffffffu, mx1, 2));
        const float mn0 = fmaxf(m0, mx0);
        const float mn1 = fmaxf(m1, mx1);
        const float fac0 = fexp2(m0 - mn0);
        const float fac1 = fexp2(m1 - mn1);
        m0 = mn0; m1 = mn1;

        // ---- exp2 + in-register P fragments ----
        float sum0 = 0.f, sum1 = 0.f;
        uint4 pf[4];
        #pragma unroll
        for (int k2 = 0; k2 < 4; k2++) {
            const int ne = 2 * k2, no = 2 * k2 + 1;
            const float p00 = fexp2(sc[ne][0] - mn0);
            const float p01 = fexp2(sc[ne][1] - mn0);
            const float p02 = fexp2(sc[ne][2] - mn1);
            const float p03 = fexp2(sc[ne][3] - mn1);
            const float p10 = fexp2(sc[no][0] - mn0);
            const float p11 = fexp2(sc[no][1] - mn0);
            const float p12 = fexp2(sc[no][2] - mn1);
            const float p13 = fexp2(sc[no][3] - mn1);
            sum0 += p00 + p01 + p10 + p11;
            sum1 += p02 + p03 + p12 + p13;
            pf[k2].x = pack_h2(p00, p01);
            pf[k2].y = pack_h2(p02, p03);
            pf[k2].z = pack_h2(p10, p11);
            pf[k2].w = pack_h2(p12, p13);
        }
        l0 = l0 * fac0 + sum0;
        l1 = l1 * fac1 + sum1;
        #pragma unroll
        for (int nt = 0; nt < 8; nt++) {
            o[nt][0] *= fac0; o[nt][1] *= fac0;
            o[nt][2] *= fac1; o[nt][3] *= fac1;
        }

        // ---- O += P V  (V frags via ldmatrix.trans) ----
        #pragma unroll
        for (int kt2 = 0; kt2 < 4; kt2++) {
            #pragma unroll
            for (int dp = 0; dp < 4; dp++) {
                uint4 r4;
                ldm_x4t(r4, vb + (uint32_t)((kt2 * 16 + vrow) * 144 + (dp * 16 + vcol) * 2));
                mma_f16(o[2 * dp],     pf[kt2], make_uint2(r4.x, r4.y));
                mma_f16(o[2 * dp + 1], pf[kt2], make_uint2(r4.z, r4.w));
            }
        }
    }

    // ---- finalize (quad-sum l, fully warp-local) ----
    l0 += __shfl_xor_sync(0xffffffffu, l0, 1);
    l0 += __shfl_xor_sync(0xffffffffu, l0, 2);
    l1 += __shfl_xor_sync(0xffffffffu, l1, 1);
    l1 += __shfl_xor_sync(0xffffffffu, l1, 2);
    const float inv0 = 1.f / l0;
    const float inv1 = 1.f / l1;

    #pragma unroll
    for (int nt = 0; nt < 8; nt++) {
        const int c = nt * 8 + (lane & 3) * 2;
        *(uint32_t*)&Oh[obase + (size_t)qrow * DM + c] =
            pack_h2(o[nt][0] * inv0, o[nt][1] * inv0);
        *(uint32_t*)&Oh[obase + (size_t)(qrow + 8) * DM + c] =
            pack_h2(o[nt][2] * inv1, o[nt][3] * inv1);
    }
}

// ---------------------------------------------------------------------------
extern "C" void kernel_launch(void* const* d_in, const int* in_sizes, int n_in,
                              void* d_out, int out_size) {
    const float* x      = (const float*)d_in[0];
    const int*   mask   = (const int*)  d_in[1];
    const float* wq     = (const float*)d_in[2];
    const float* bq     = (const float*)d_in[3];
    const float* wk     = (const float*)d_in[4];
    const float* bk     = (const float*)d_in[5];
    const float* wv     = (const float*)d_in[6];
    const float* bv     = (const float*)d_in[7];
    const float* wo     = (const float*)d_in[8];
    const float* bo     = (const float*)d_in[9];
    const float* w1     = (const float*)d_in[10];
    const float* b1     = (const float*)d_in[11];
    const float* w2     = (const float*)d_in[12];
    const float* b2     = (const float*)d_in[13];
    const float* alpha1 = (const float*)d_in[14];
    const float* beta1  = (const float*)d_in[15];
    const float* alpha2 = (const float*)d_in[16];
    const float* beta2  = (const float*)d_in[17];
    float* out = (float*)d_out;

    __half *h, *qkv, *ctx, *ff;
    float *x2, *bqkv;
    uint32_t *wqkvf, *wof, *w1f, *w2f;
    cudaGetSymbolAddress((void**)&h,     g_h);
    cudaGetSymbolAddress((void**)&qkv,   g_qkv);
    cudaGetSymbolAddress((void**)&ctx,   g_ctx);
    cudaGetSymbolAddress((void**)&x2,    g_x2);
    cudaGetSymbolAddress((void**)&ff,    g_ff);
    cudaGetSymbolAddress((void**)&bqkv,  g_bqkv);
    cudaGetSymbolAddress((void**)&wqkvf, g_wqkvf);
    cudaGetSymbolAddress((void**)&wof,   g_wof);
    cudaGetSymbolAddress((void**)&w1f,   g_w1f);
    cudaGetSymbolAddress((void**)&w2f,   g_w2f);

    cudaFuncSetAttribute((const void*)gemm_mma<0, 4>, cudaFuncAttributeMaxDynamicSharedMemorySize, G_DSMEM(4));
    cudaFuncSetAttribute((const void*)gemm_mma<1, 4>, cudaFuncAttributeMaxDynamicSharedMemorySize, G_DSMEM(4));
    cudaFuncSetAttribute((const void*)gemm_mma<2, 2>, cudaFuncAttributeMaxDynamicSharedMemorySize, G_DSMEM(2));
    cudaFuncSetAttribute((const void*)attn_mma,       cudaFuncAttributeMaxDynamicSharedMemorySize, A_DSMEM);

    // 0. weight prep (fragment layouts; q,k,v tiles contiguous in one buffer)
    prep_w<<<DM * DM / 2 / 256, 256>>>(wq, wqkvf, DM);
    prep_w<<<DM * DM / 2 / 256, 256>>>(wk, wqkvf + DM * DM / 2, DM);
    prep_w<<<DM * DM / 2 / 256, 256>>>(wv, wqkvf + DM * DM, DM);
    prep_w<<<DM * DM / 2 / 256, 256>>>(wo, wof, DM);
    prep_w<<<DFF * DM / 2 / 256, 256>>>(w1, w1f, DM);
    prep_w<<<DM * DFF / 2 / 256, 256>>>(w2, w2f, DFF);
    cat_bias<<<9, 256>>>(bq, bk, bv, bqkv);

    const dim3 g_qkvg(QS / 128, NTOK / 128);   // (18, 64) fused qkv
    const dim3 g_n768(DM / 128, NTOK / 64);    // (6, 128) M64 tiles
    const dim3 g_ff1(DFF / 128, NTOK / 128);   // (24, 64)
    const dim3 attn_grid(S_LEN / 128, NH, BATCH);

    // 1. h = norm1(x)  (half out)
    norm_kernel<<<NTOK, 256>>>(x, h, alpha1, beta1);
    // 2. fused qkv projection -> [NTOK][2304]
    gemm_mma<0, 4><<<g_qkvg, 256, G_DSMEM(4)>>>(h, wqkvf, bqkv, nullptr, qkv, NTOK, QS, DM);
    // 3. attention -> ctx
    attn_mma<<<attn_grid, 256, A_DSMEM>>>(qkv, mask, ctx);
    // 4. x2 = x + ctx @ wo^T + bo  (f32 out, M64 tiles)
    gemm_mma<2, 2><<<g_n768, 256, G_DSMEM(2)>>>(ctx, wof, bo, x, x2, NTOK, DM, DM);
    // 5. h = norm2(x2) (half out)
    norm_kernel<<<NTOK, 256>>>(x2, h, alpha2, beta2);
    // 6. ff = relu(h @ w1^T + b1)  (half out)
    gemm_mma<1, 4><<<g_ff1, 256, G_DSMEM(4)>>>(h, w1f, b1, nullptr, ff, NTOK, DFF, DM);
    // 7. out = x2 + ff @ w2^T + b2 (f32 out, M64 tiles)
    gemm_mma<2, 2><<<g_n768, 256, G_DSMEM(2)>>>(ff, w2f, b2, x2, out, NTOK, DM, DFF);
}

// round 16
// speedup vs baseline: 1.0421x; 1.0421x over previous
#include <cuda_runtime.h>
#include <cuda_fp16.h>
#include <cstdint>
#include <math.h>

#define S_LEN 4096
#define BATCH 2
#define DM    768
#define DFF   3072
#define NH    12
#define DK    64
#define NTOK  (BATCH * S_LEN)

// ---------------- scratch (device globals: no allocation allowed) ----------
__device__ __half g_h  [NTOK * DM];
__device__ __half g_q  [NTOK * DM];
__device__ __half g_k  [NTOK * DM];
__device__ __half g_v  [NTOK * DM];
__device__ __half g_ctx[NTOK * DM];
__device__ float  g_x2 [NTOK * DM];
__device__ __half g_ff [NTOK * DFF];
// weight fragments (u32 = f16x2), layout [ntile][ktile][2048]
__device__ uint32_t g_wqf[DM * DM / 2];
__device__ uint32_t g_wkf[DM * DM / 2];
__device__ uint32_t g_wvf[DM * DM / 2];
__device__ uint32_t g_wof[DM * DM / 2];
__device__ uint32_t g_w1f[DFF * DM / 2];
__device__ uint32_t g_w2f[DM * DFF / 2];

// ---------------- helpers --------------------------------------------------
__device__ __forceinline__ uint32_t pack_h2(float lo, float hi) {
    uint32_t r; asm("cvt.rn.f16x2.f32 %0, %1, %2;" : "=r"(r) : "f"(hi), "f"(lo)); return r;
}
__device__ __forceinline__ float fexp2(float x) {
    float r; asm("ex2.approx.f32 %0, %1;" : "=f"(r) : "f"(x)); return r;
}

__device__ __forceinline__ void mma_f16(float c[4], const uint4& a, const uint2& b) {
    asm volatile(
        "mma.sync.aligned.m16n8k16.row.col.f32.f16.f16.f32 "
        "{%0,%1,%2,%3}, {%4,%5,%6,%7}, {%8,%9}, {%0,%1,%2,%3};"
        : "+f"(c[0]), "+f"(c[1]), "+f"(c[2]), "+f"(c[3])
        : "r"(a.x), "r"(a.y), "r"(a.z), "r"(a.w), "r"(b.x), "r"(b.y));
}

#define CP16(dst, src) \
    asm volatile("cp.async.ca.shared.global [%0], [%1], 16;" :: "r"(dst), "l"(src))
#define CP_COMMIT() asm volatile("cp.async.commit_group;" ::: "memory")
#define CP_WAIT(N)  asm volatile("cp.async.wait_group %0;" :: "n"(N) : "memory")

__device__ __forceinline__ void ldm_x4(uint4& r, uint32_t a) {
    asm volatile("ldmatrix.sync.aligned.m8n8.x4.shared.b16 {%0,%1,%2,%3}, [%4];"
        : "=r"(r.x), "=r"(r.y), "=r"(r.z), "=r"(r.w) : "r"(a));
}
__device__ __forceinline__ void ldm_x4t(uint4& r, uint32_t a) {
    asm volatile("ldmatrix.sync.aligned.m8n8.x4.trans.shared.b16 {%0,%1,%2,%3}, [%4];"
        : "=r"(r.x), "=r"(r.y), "=r"(r.z), "=r"(r.w) : "r"(a));
}

// ---------------- fused weight prep: one launch for all 6 matrices ---------
// f32 [N][K] -> B-fragment half layout, block-range dispatch.
__device__ __forceinline__ void prep_one(const float* W, uint32_t* out, int K, int idx) {
    const int tile = idx >> 11, j = idx & 2047;
    const int ktiles = K >> 5;
    const int ntile = tile / ktiles, ktile = tile - ntile * ktiles;
    const int reg = j & 1, lane = (j >> 1) & 31, nt = (j >> 6) & 15, kt = j >> 10;
    const int n = ntile * 128 + nt * 8 + (lane >> 2);
    const int k = ktile * 32 + kt * 16 + (lane & 3) * 2 + 8 * reg;
    out[idx] = pack_h2(W[(size_t)n * K + k], W[(size_t)n * K + k + 1]);
}

// blocks: wq[0,1152) wk[1152,2304) wv[2304,3456) wo[3456,4608)
//         w1[4608,9216) w2[9216,13824)
__global__ void prep_all(const float* __restrict__ wq, const float* __restrict__ wk,
                         const float* __restrict__ wv, const float* __restrict__ wo,
                         const float* __restrict__ w1, const float* __restrict__ w2) {
    const int bb = blockIdx.x;
    if (bb < 1152)       prep_one(wq, g_wqf, DM,  bb * 256 + threadIdx.x);
    else if (bb < 2304)  prep_one(wk, g_wkf, DM,  (bb - 1152) * 256 + threadIdx.x);
    else if (bb < 3456)  prep_one(wv, g_wvf, DM,  (bb - 2304) * 256 + threadIdx.x);
    else if (bb < 4608)  prep_one(wo, g_wof, DM,  (bb - 3456) * 256 + threadIdx.x);
    else if (bb < 9216)  prep_one(w1, g_w1f, DM,  (bb - 4608) * 256 + threadIdx.x);
    else                 prep_one(w2, g_w2f, DFF, (bb - 9216) * 256 + threadIdx.x);
}

// ---------------- layernorm-ish: one warp per row, no block barriers -------
__global__ void norm_kernel(const float* __restrict__ x, __half* __restrict__ out,
                            const float* __restrict__ alpha, const float* __restrict__ beta) {
    const int warp = threadIdx.x >> 5, lane = threadIdx.x & 31;
    const int row = blockIdx.x * 8 + warp;
    const float* xr = x + (size_t)row * DM;

    float4 v[6];
    float s = 0.f, sq = 0.f;
    #pragma unroll
    for (int c = 0; c < 6; c++) {
        v[c] = *(const float4*)(xr + c * 128 + lane * 4);
        s  += (v[c].x + v[c].y) + (v[c].z + v[c].w);
        sq += v[c].x * v[c].x + v[c].y * v[c].y + v[c].z * v[c].z + v[c].w * v[c].w;
    }
    #pragma unroll
    for (int o = 16; o > 0; o >>= 1) {
        s  += __shfl_xor_sync(0xffffffffu, s,  o);
        sq += __shfl_xor_sync(0xffffffffu, sq, o);
    }
    const float mean = s / (float)DM;
    float var = (sq - (float)DM * mean * mean) / (float)(DM - 1);
    var = fmaxf(var, 0.f);
    const float scale = alpha[0] / (sqrtf(var) + 1e-6f);
    const float bb = beta[0];

    __half* orow = out + (size_t)row * DM;
    #pragma unroll
    for (int c = 0; c < 6; c++) {
        uint2 pk;
        pk.x = pack_h2((v[c].x - mean) * scale + bb, (v[c].y - mean) * scale + bb);
        pk.y = pack_h2((v[c].z - mean) * scale + bb, (v[c].w - mean) * scale + bb);
        *(uint2*)(orow + c * 128 + lane * 4) = pk;
    }
}

// =================== fp16 GEMM: cp.async + ldmatrix A, pre-fragged B =======
// C = A[M,K] @ W[N,K]^T (+bias).  MODE 0: half out. 1: half+relu. 2: f32+res.
// 3-stage ring, distance-1 prefetch, 1 sync/iter.
// A tile: 128 rows x 32 halves row-major, 80B row stride (bank-conflict-free).
#define G_STG   18432                     // 10240 (A) + 8192 (B)
#define G_DSMEM (3 * G_STG)

template <int MODE>
__global__ void __launch_bounds__(256, 2)
gemm_mma(const __half* __restrict__ A, const uint32_t* __restrict__ Wf,
         const float* __restrict__ bias, const float* __restrict__ res,
         void* __restrict__ Cv, int M, int N, int K) {
    extern __shared__ char smc[];
    const uint32_t sb = (uint32_t)__cvta_generic_to_shared(smc);

    const int t    = threadIdx.x;
    const int lane = t & 31;
    const int wid  = t >> 5;
    const int wy   = wid >> 2;
    const int wx   = wid & 3;
    const int bm   = blockIdx.y * 128;
    const int bn   = blockIdx.x * 128;

    const __half* Ab = A + (size_t)bm * K;
    const uint32_t* Wtile0 = Wf + (size_t)(bn >> 7) * (K >> 5) * 2048;

    float acc[4][4][4];
    #pragma unroll
    for (int i = 0; i < 4; i++)
        #pragma unroll
        for (int j = 0; j < 4; j++)
            #pragma unroll
            for (int r = 0; r < 4; r++) acc[i][j][r] = 0.f;

    const int arowp = t >> 2, achp = t & 3;

    auto stage = [&](int ktile, int s) {
        const uint32_t ab = sb + s * G_STG;
        #pragma unroll
        for (int p = 0; p < 2; p++) {
            const int row = arowp + p * 64;
            CP16(ab + row * 80 + achp * 16,
                 (const char*)(Ab + (size_t)row * K + ktile * 32) + achp * 16);
        }
        const uint32_t bb = ab + 10240;
        const char* wsrc = (const char*)(Wtile0 + (size_t)ktile * 2048);
        CP16(bb + t * 16,         wsrc + t * 16);
        CP16(bb + (t + 256) * 16, wsrc + (t + 256) * 16);
    };

    const int army = ((lane >> 3) & 1) * 8 + (lane & 7);
    const int acol = ((lane >> 4) & 1) * 8;

    auto compute = [&](int s) {
        const uint32_t ab = sb + s * G_STG;
        const uint32_t* Bs = (const uint32_t*)(smc + s * G_STG + 10240);
        #pragma unroll
        for (int kt = 0; kt < 2; kt++) {
            uint4 af[4];
            #pragma unroll
            for (int mt = 0; mt < 4; mt++)
                ldm_x4(af[mt], ab + (uint32_t)((wy * 64 + mt * 16 + army) * 80
                                               + (kt * 16 + acol) * 2));
            uint2 bf[4];
            #pragma unroll
            for (int nt = 0; nt < 4; nt++)
                bf[nt] = *(const uint2*)&Bs[((kt * 16 + wx * 4 + nt) * 32 + lane) * 2];
            #pragma unroll
            for (int mt = 0; mt < 4; mt++)
                #pragma unroll
                for (int nt = 0; nt < 4; nt++)
                    mma_f16(acc[mt][nt], af[mt], bf[nt]);
        }
    };

    const int niter = K / 32;

    stage(0, 0);
    CP_COMMIT();
    for (int i = 0; i < niter; i++) {
        if (i + 1 < niter) {
            stage(i + 1, (i + 1) % 3);
            CP_COMMIT();
            CP_WAIT(1);
        } else {
            CP_WAIT(0);
        }
        __syncthreads();
        compute(i % 3);
    }

    const int rbase = bm + wy * 64 + (lane >> 2);
    const int cbase = bn + wx * 32 + (lane & 3) * 2;
    #pragma unroll
    for (int mt = 0; mt < 4; mt++) {
        #pragma unroll
        for (int nt = 0; nt < 4; nt++) {
            const int c = cbase + nt * 8;
            const float b0 = bias[c], b1 = bias[c + 1];
            const int r0 = rbase + mt * 16;
            const int r1 = r0 + 8;
            float v0 = acc[mt][nt][0] + b0;
            float v1 = acc[mt][nt][1] + b1;
            float v2 = acc[mt][nt][2] + b0;
            float v3 = acc[mt][nt][3] + b1;
            if (MODE == 1) {
                v0 = fmaxf(v0, 0.f); v1 = fmaxf(v1, 0.f);
                v2 = fmaxf(v2, 0.f); v3 = fmaxf(v3, 0.f);
            }
            if (MODE == 2) {
                const float2 q0 = *(const float2*)&res[(size_t)r0 * N + c];
                const float2 q1 = *(const float2*)&res[(size_t)r1 * N + c];
                float* C = (float*)Cv;
                *(float2*)&C[(size_t)r0 * N + c] = make_float2(v0 + q0.x, v1 + q0.y);
                *(float2*)&C[(size_t)r1 * N + c] = make_float2(v2 + q1.x, v3 + q1.y);
            } else {
                __half* C = (__half*)Cv;
                *(uint32_t*)&C[(size_t)r0 * N + c] = pack_h2(v0, v1);
                *(uint32_t*)&C[(size_t)r1 * N + c] = pack_h2(v2, v3);
            }
        }
    }
}

// =================== fp16 flash attention: cp.async + ldmatrix =============
// CTA: 128 queries (one (b,h)); 8 warps x 16 queries; BN=64 keys/iter.
// K,V row-major in smem (144B row stride), frags via ldmatrix / ldmatrix.trans.
// 3-stage ring, 1 sync/iter, register-resident P, log2-domain softmax.
#define A_STG   18688                 // K 9216 + V 9216 + mask 256
#define A_DSMEM (3 * A_STG)
#define SCL2    0.1803368801f         // 0.125 * log2(e)

__global__ void __launch_bounds__(256, 2)
attn_mma(const __half* __restrict__ Qh, const __half* __restrict__ Kh,
         const __half* __restrict__ Vh, const int* __restrict__ mask,
         __half* __restrict__ Oh) {
    extern __shared__ char smc[];
    const uint32_t sb = (uint32_t)__cvta_generic_to_shared(smc);

    const int t = threadIdx.x, lane = t & 31, wid = t >> 5;
    const int q0 = blockIdx.x * 128;
    const int h  = blockIdx.y, b = blockIdx.z;
    const size_t base = (size_t)b * S_LEN * DM + (size_t)h * DK;

    // ---- persistent Q A-fragments (16 queries per warp) ----
    const int qrow = q0 + wid * 16 + (lane >> 2);
    uint4 aq[4];
    #pragma unroll
    for (int kt = 0; kt < 4; kt++) {
        const __half* qp = Qh + base + (size_t)qrow * DM + kt * 16 + (lane & 3) * 2;
        aq[kt].x = *(const uint32_t*)qp;
        aq[kt].y = *(const uint32_t*)(qp + (size_t)8 * DM);
        aq[kt].z = *(const uint32_t*)(qp + 8);
        aq[kt].w = *(const uint32_t*)(qp + (size_t)8 * DM + 8);
    }

    float m0 = -INFINITY, m1 = -INFINITY, l0 = 0.f, l1 = 0.f;
    float o[8][4];
    #pragma unroll
    for (int i = 0; i < 8; i++)
        #pragma unroll
        for (int j = 0; j < 4; j++) o[i][j] = 0.f;

    const int srow = t >> 3, sch = t & 7;

    auto stage = [&](int ks0, int s) {
        const uint32_t kb = sb + s * A_STG;
        #pragma unroll
        for (int p = 0; p < 2; p++) {
            const int row = srow + p * 32;
            CP16(kb + row * 144 + sch * 16,
                 (const char*)(Kh + base + (size_t)(ks0 + row) * DM) + sch * 16);
            CP16(kb + 9216 + row * 144 + sch * 16,
                 (const char*)(Vh + base + (size_t)(ks0 + row) * DM) + sch * 16);
        }
        if (t < 16)
            CP16(kb + 18432 + t * 16, (const char*)(mask + (size_t)b * S_LEN + ks0) + t * 16);
    };

    const int krow = ((lane >> 4) & 1) * 8 + (lane & 7);
    const int kcol = ((lane >> 3) & 1) * 8;
    const int vrow = ((lane >> 3) & 1) * 8 + (lane & 7);
    const int vcol = ((lane >> 4) & 1) * 8;

    stage(0, 0);
    CP_COMMIT();

    for (int i = 0; i < 64; i++) {
        if (i + 1 < 64) {
            stage((i + 1) * 64, (i + 1) % 3);
            CP_COMMIT();
            CP_WAIT(1);
        } else {
            CP_WAIT(0);
        }
        __syncthreads();
        const int s = i % 3;
        const uint32_t kb = sb + s * A_STG;
        const uint32_t vb = kb + 9216;
        const int* mk = (const int*)(smc + s * A_STG + 18432);

        // ---- S = Q K^T ----
        float sc[8][4];
        #pragma unroll
        for (int nt = 0; nt < 8; nt++)
            #pragma unroll
            for (int r = 0; r < 4; r++) sc[nt][r] = 0.f;
        #pragma unroll
        for (int kt = 0; kt < 4; kt++) {
            uint2 bf[8];
            #pragma unroll
            for (int kg = 0; kg < 4; kg++) {
                uint4 r4;
                ldm_x4(r4, kb + (uint32_t)((kg * 16 + krow) * 144 + (kt * 16 + kcol) * 2));
                bf[2 * kg]     = make_uint2(r4.x, r4.y);
                bf[2 * kg + 1] = make_uint2(r4.z, r4.w);
            }
            #pragma unroll
            for (int nt = 0; nt < 8; nt++)
                mma_f16(sc[nt], aq[kt], bf[nt]);
        }

        // ---- mask + log2-scale + in-register row max ----
        float mx0 = -INFINITY, mx1 = -INFINITY;
        #pragma unroll
        for (int nt = 0; nt < 8; nt++) {
            const int c = nt * 8 + (lane & 3) * 2;
            const int2 mm = *(const int2*)&mk[c];
            const bool ma = mm.x != 0, mb = mm.y != 0;
            sc[nt][0] = ma ? sc[nt][0] * SCL2 : -1e9f;
            sc[nt][1] = mb ? sc[nt][1] * SCL2 : -1e9f;
            sc[nt][2] = ma ? sc[nt][2] * SCL2 : -1e9f;
            sc[nt][3] = mb ? sc[nt][3] * SCL2 : -1e9f;
            mx0 = fmaxf(mx0, fmaxf(sc[nt][0], sc[nt][1]));
            mx1 = fmaxf(mx1, fmaxf(sc[nt][2], sc[nt][3]));
        }
        mx0 = fmaxf(mx0, __shfl_xor_sync(0xffffffffu, mx0, 1));
        mx0 = fmaxf(mx0, __shfl_xor_sync(0xffffffffu, mx0, 2));
        mx1 = fmaxf(mx1, __shfl_xor_sync(0xffffffffu, mx1, 1));
        mx1 = fmaxf(mx1, __shfl_xor_sync(0xffffffffu, mx1, 2));
        const float mn0 = fmaxf(m0, mx0);
        const float mn1 = fmaxf(m1, mx1);
        const float fac0 = fexp2(m0 - mn0);
        const float fac1 = fexp2(m1 - mn1);
        m0 = mn0; m1 = mn1;

        // ---- exp2 + in-register P fragments ----
        float sum0 = 0.f, sum1 = 0.f;
        uint4 pf[4];
        #pragma unroll
        for (int k2 = 0; k2 < 4; k2++) {
            const int ne = 2 * k2, no = 2 * k2 + 1;
            const float p00 = fexp2(sc[ne][0] - mn0);
            const float p01 = fexp2(sc[ne][1] - mn0);
            const float p02 = fexp2(sc[ne][2] - mn1);
            const float p03 = fexp2(sc[ne][3] - mn1);
            const float p10 = fexp2(sc[no][0] - mn0);
            const float p11 = fexp2(sc[no][1] - mn0);
            const float p12 = fexp2(sc[no][2] - mn1);
            const float p13 = fexp2(sc[no][3] - mn1);
            sum0 += p00 + p01 + p10 + p11;
            sum1 += p02 + p03 + p12 + p13;
            pf[k2].x = pack_h2(p00, p01);
            pf[k2].y = pack_h2(p02, p03);
            pf[k2].z = pack_h2(p10, p11);
            pf[k2].w = pack_h2(p12, p13);
        }
        l0 = l0 * fac0 + sum0;
        l1 = l1 * fac1 + sum1;
        #pragma unroll
        for (int nt = 0; nt < 8; nt++) {
            o[nt][0] *= fac0; o[nt][1] *= fac0;
            o[nt][2] *= fac1; o[nt][3] *= fac1;
        }

        // ---- O += P V  (V frags via ldmatrix.trans) ----
        #pragma unroll
        for (int kt2 = 0; kt2 < 4; kt2++) {
            #pragma unroll
            for (int dp = 0; dp < 4; dp++) {
                uint4 r4;
                ldm_x4t(r4, vb + (uint32_t)((kt2 * 16 + vrow) * 144 + (dp * 16 + vcol) * 2));
                mma_f16(o[2 * dp],     pf[kt2], make_uint2(r4.x, r4.y));
                mma_f16(o[2 * dp + 1], pf[kt2], make_uint2(r4.z, r4.w));
            }
        }
    }

    // ---- finalize (quad-sum l, fully warp-local) ----
    l0 += __shfl_xor_sync(0xffffffffu, l0, 1);
    l0 += __shfl_xor_sync(0xffffffffu, l0, 2);
    l1 += __shfl_xor_sync(0xffffffffu, l1, 1);
    l1 += __shfl_xor_sync(0xffffffffu, l1, 2);
    const float inv0 = 1.f / l0;
    const float inv1 = 1.f / l1;

    #pragma unroll
    for (int nt = 0; nt < 8; nt++) {
        const int c = nt * 8 + (lane & 3) * 2;
        *(uint32_t*)&Oh[base + (size_t)qrow * DM + c] =
            pack_h2(o[nt][0] * inv0, o[nt][1] * inv0);
        *(uint32_t*)&Oh[base + (size_t)(qrow + 8) * DM + c] =
            pack_h2(o[nt][2] * inv1, o[nt][3] * inv1);
    }
}

// ---------------------------------------------------------------------------
extern "C" void kernel_launch(void* const* d_in, const int* in_sizes, int n_in,
                              void* d_out, int out_size) {
    const float* x      = (const float*)d_in[0];
    const int*   mask   = (const int*)  d_in[1];
    const float* wq     = (const float*)d_in[2];
    const float* bq     = (const float*)d_in[3];
    const float* wk     = (const float*)d_in[4];
    const float* bk     = (const float*)d_in[5];
    const float* wv     = (const float*)d_in[6];
    const float* bv     = (const float*)d_in[7];
    const float* wo     = (const float*)d_in[8];
    const float* bo     = (const float*)d_in[9];
    const float* w1     = (const float*)d_in[10];
    const float* b1     = (const float*)d_in[11];
    const float* w2     = (const float*)d_in[12];
    const float* b2     = (const float*)d_in[13];
    const float* alpha1 = (const float*)d_in[14];
    const float* beta1  = (const float*)d_in[15];
    const float* alpha2 = (const float*)d_in[16];
    const float* beta2  = (const float*)d_in[17];
    float* out = (float*)d_out;

    __half *h, *q, *k, *v, *ctx, *ff;
    float* x2;
    uint32_t *wqf, *wkf, *wvf, *wof, *w1f, *w2f;
    cudaGetSymbolAddress((void**)&h,   g_h);
    cudaGetSymbolAddress((void**)&q,   g_q);
    cudaGetSymbolAddress((void**)&k,   g_k);
    cudaGetSymbolAddress((void**)&v,   g_v);
    cudaGetSymbolAddress((void**)&ctx, g_ctx);
    cudaGetSymbolAddress((void**)&x2,  g_x2);
    cudaGetSymbolAddress((void**)&ff,  g_ff);
    cudaGetSymbolAddress((void**)&wqf, g_wqf);
    cudaGetSymbolAddress((void**)&wkf, g_wkf);
    cudaGetSymbolAddress((void**)&wvf, g_wvf);
    cudaGetSymbolAddress((void**)&wof, g_wof);
    cudaGetSymbolAddress((void**)&w1f, g_w1f);
    cudaGetSymbolAddress((void**)&w2f, g_w2f);

    cudaFuncSetAttribute(gemm_mma<0>, cudaFuncAttributeMaxDynamicSharedMemorySize, G_DSMEM);
    cudaFuncSetAttribute(gemm_mma<1>, cudaFuncAttributeMaxDynamicSharedMemorySize, G_DSMEM);
    cudaFuncSetAttribute(gemm_mma<2>, cudaFuncAttributeMaxDynamicSharedMemorySize, G_DSMEM);
    cudaFuncSetAttribute(attn_mma,    cudaFuncAttributeMaxDynamicSharedMemorySize, A_DSMEM);

    // 0. weight prep (one fused launch for all 6 matrices)
    prep_all<<<13824, 256>>>(wq, wk, wv, wo, w1, w2);

    const dim3 g_qkv(DM / 128,  NTOK / 128);   // (6, 64)
    const dim3 g_ff1(DFF / 128, NTOK / 128);   // (24, 64)
    const dim3 attn_grid(S_LEN / 128, NH, BATCH);

    // 1. h = norm1(x)  (half out, warp-per-row)
    norm_kernel<<<NTOK / 8, 256>>>(x, h, alpha1, beta1);
    // 2-4. q,k,v projections
    gemm_mma<0><<<g_qkv, 256, G_DSMEM>>>(h, wqf, bq, nullptr, q, NTOK, DM, DM);
    gemm_mma<0><<<g_qkv, 256, G_DSMEM>>>(h, wkf, bk, nullptr, k, NTOK, DM, DM);
    gemm_mma<0><<<g_qkv, 256, G_DSMEM>>>(h, wvf, bv, nullptr, v, NTOK, DM, DM);
    // 5. attention -> ctx
    attn_mma<<<attn_grid, 256, A_DSMEM>>>(q, k, v, mask, ctx);
    // 6. x2 = x + ctx @ wo^T + bo  (f32 out)
    gemm_mma<2><<<g_qkv, 256, G_DSMEM>>>(ctx, wof, bo, x, x2, NTOK, DM, DM);
    // 7. h = norm2(x2) (half out)
    norm_kernel<<<NTOK / 8, 256>>>(x2, h, alpha2, beta2);
    // 8. ff = relu(h @ w1^T + b1)  (half out)
    gemm_mma<1><<<g_ff1, 256, G_DSMEM>>>(h, w1f, b1, nullptr, ff, NTOK, DFF, DM);
    // 9. out = x2 + ff @ w2^T + b2 (f32 out)
    gemm_mma<2><<<g_qkv, 256, G_DSMEM>>>(ff, w2f, b2, x2, out, NTOK, DM, DFF);
}

// round 17
// speedup vs baseline: 1.0649x; 1.0219x over previous
#include <cuda_runtime.h>
#include <cuda_fp16.h>
#include <cstdint>
#include <math.h>

#define S_LEN 4096
#define BATCH 2
#define DM    768
#define DFF   3072
#define NH    12
#define DK    64
#define NTOK  (BATCH * S_LEN)
#define QS    2304

// ---------------- scratch (device globals: no allocation allowed) ----------
__device__ __half g_h  [NTOK * DM];
__device__ __half g_q  [NTOK * DM];
__device__ __half g_k  [NTOK * DM];
__device__ __half g_v  [NTOK * DM];
__device__ __half g_ctx[NTOK * DM];
__device__ float  g_x2 [NTOK * DM];
__device__ __half g_ff [NTOK * DFF];
__device__ float  g_bqkv[QS];
// weight fragments (u32 = f16x2), layout [ntile][ktile][2048]
__device__ uint32_t g_wqkvf[3 * DM * DM / 2];   // q tiles, then k, then v
__device__ uint32_t g_wof  [DM * DM / 2];
__device__ uint32_t g_w1f  [DFF * DM / 2];
__device__ uint32_t g_w2f  [DM * DFF / 2];

// ---------------- helpers --------------------------------------------------
__device__ __forceinline__ uint32_t pack_h2(float lo, float hi) {
    uint32_t r; asm("cvt.rn.f16x2.f32 %0, %1, %2;" : "=r"(r) : "f"(hi), "f"(lo)); return r;
}
__device__ __forceinline__ float fexp2(float x) {
    float r; asm("ex2.approx.f32 %0, %1;" : "=f"(r) : "f"(x)); return r;
}

__device__ __forceinline__ void mma_f16(float c[4], const uint4& a, const uint2& b) {
    asm volatile(
        "mma.sync.aligned.m16n8k16.row.col.f32.f16.f16.f32 "
        "{%0,%1,%2,%3}, {%4,%5,%6,%7}, {%8,%9}, {%0,%1,%2,%3};"
        : "+f"(c[0]), "+f"(c[1]), "+f"(c[2]), "+f"(c[3])
        : "r"(a.x), "r"(a.y), "r"(a.z), "r"(a.w), "r"(b.x), "r"(b.y));
}

#define CP16(dst, src) \
    asm volatile("cp.async.ca.shared.global [%0], [%1], 16;" :: "r"(dst), "l"(src))
#define CP_COMMIT() asm volatile("cp.async.commit_group;" ::: "memory")
#define CP_WAIT(N)  asm volatile("cp.async.wait_group %0;" :: "n"(N) : "memory")

__device__ __forceinline__ void ldm_x4(uint4& r, uint32_t a) {
    asm volatile("ldmatrix.sync.aligned.m8n8.x4.shared.b16 {%0,%1,%2,%3}, [%4];"
        : "=r"(r.x), "=r"(r.y), "=r"(r.z), "=r"(r.w) : "r"(a));
}
__device__ __forceinline__ void ldm_x4t(uint4& r, uint32_t a) {
    asm volatile("ldmatrix.sync.aligned.m8n8.x4.trans.shared.b16 {%0,%1,%2,%3}, [%4];"
        : "=r"(r.x), "=r"(r.y), "=r"(r.z), "=r"(r.w) : "r"(a));
}

// ---------------- fused weight prep: one launch for all matrices ----------
__device__ __forceinline__ void prep_one(const float* W, uint32_t* out, int K, int idx) {
    const int tile = idx >> 11, j = idx & 2047;
    const int ktiles = K >> 5;
    const int ntile = tile / ktiles, ktile = tile - ntile * ktiles;
    const int reg = j & 1, lane = (j >> 1) & 31, nt = (j >> 6) & 15, kt = j >> 10;
    const int n = ntile * 128 + nt * 8 + (lane >> 2);
    const int k = ktile * 32 + kt * 16 + (lane & 3) * 2 + 8 * reg;
    out[idx] = pack_h2(W[(size_t)n * K + k], W[(size_t)n * K + k + 1]);
}

// blocks: wq[0,1152) wk[1152,2304) wv[2304,3456) wo[3456,4608)
//         w1[4608,9216) w2[9216,13824)
__global__ void prep_all(const float* __restrict__ wq, const float* __restrict__ wk,
                         const float* __restrict__ wv, const float* __restrict__ wo,
                         const float* __restrict__ w1, const float* __restrict__ w2) {
    const int bb = blockIdx.x;
    if (bb < 1152)       prep_one(wq, g_wqkvf,               DM,  bb * 256 + threadIdx.x);
    else if (bb < 2304)  prep_one(wk, g_wqkvf + DM * DM / 2, DM,  (bb - 1152) * 256 + threadIdx.x);
    else if (bb < 3456)  prep_one(wv, g_wqkvf + DM * DM,     DM,  (bb - 2304) * 256 + threadIdx.x);
    else if (bb < 4608)  prep_one(wo, g_wof, DM,  (bb - 3456) * 256 + threadIdx.x);
    else if (bb < 9216)  prep_one(w1, g_w1f, DM,  (bb - 4608) * 256 + threadIdx.x);
    else                 prep_one(w2, g_w2f, DFF, (bb - 9216) * 256 + threadIdx.x);
}

__global__ void cat_bias(const float* __restrict__ a, const float* __restrict__ b,
                         const float* __restrict__ c, float* __restrict__ o) {
    const int i = blockIdx.x * 256 + threadIdx.x;
    if (i < QS)
        o[i] = i < 768 ? a[i] : (i < 1536 ? b[i - 768] : c[i - 1536]);
}

// ---------------- layernorm-ish: one warp per row, no block barriers -------
__global__ void norm_kernel(const float* __restrict__ x, __half* __restrict__ out,
                            const float* __restrict__ alpha, const float* __restrict__ beta) {
    const int warp = threadIdx.x >> 5, lane = threadIdx.x & 31;
    const int row = blockIdx.x * 8 + warp;
    const float* xr = x + (size_t)row * DM;

    float4 v[6];
    float s = 0.f, sq = 0.f;
    #pragma unroll
    for (int c = 0; c < 6; c++) {
        v[c] = *(const float4*)(xr + c * 128 + lane * 4);
        s  += (v[c].x + v[c].y) + (v[c].z + v[c].w);
        sq += v[c].x * v[c].x + v[c].y * v[c].y + v[c].z * v[c].z + v[c].w * v[c].w;
    }
    #pragma unroll
    for (int o = 16; o > 0; o >>= 1) {
        s  += __shfl_xor_sync(0xffffffffu, s,  o);
        sq += __shfl_xor_sync(0xffffffffu, sq, o);
    }
    const float mean = s / (float)DM;
    float var = (sq - (float)DM * mean * mean) / (float)(DM - 1);
    var = fmaxf(var, 0.f);
    const float scale = alpha[0] / (sqrtf(var) + 1e-6f);
    const float bb = beta[0];

    __half* orow = out + (size_t)row * DM;
    #pragma unroll
    for (int c = 0; c < 6; c++) {
        uint2 pk;
        pk.x = pack_h2((v[c].x - mean) * scale + bb, (v[c].y - mean) * scale + bb);
        pk.y = pack_h2((v[c].z - mean) * scale + bb, (v[c].w - mean) * scale + bb);
        *(uint2*)(orow + c * 128 + lane * 4) = pk;
    }
}

// =================== fp16 GEMM: cp.async + ldmatrix A, pre-fragged B =======
// C = A[M,K] @ W[N,K]^T (+bias).
// MODE 0: half out. 1: half+relu. 2: f32+res. 3: fused-qkv split (3 half outs,
//         each stride DM; CTA's 128-col tile lies wholly in one of q/k/v).
// 3-stage ring, distance-1 prefetch, 1 sync/iter.
#define G_STG   18432                     // 10240 (A) + 8192 (B)
#define G_DSMEM (3 * G_STG)

template <int MODE>
__global__ void __launch_bounds__(256, 2)
gemm_mma(const __half* __restrict__ A, const uint32_t* __restrict__ Wf,
         const float* __restrict__ bias, const float* __restrict__ res,
         void* __restrict__ Cv, void* __restrict__ Cv2, void* __restrict__ Cv3,
         int M, int N, int K) {
    extern __shared__ char smc[];
    const uint32_t sb = (uint32_t)__cvta_generic_to_shared(smc);

    const int t    = threadIdx.x;
    const int lane = t & 31;
    const int wid  = t >> 5;
    const int wy   = wid >> 2;
    const int wx   = wid & 3;
    const int bm   = blockIdx.y * 128;
    const int bn   = blockIdx.x * 128;

    const __half* Ab = A + (size_t)bm * K;
    const uint32_t* Wtile0 = Wf + (size_t)(bn >> 7) * (K >> 5) * 2048;

    float acc[4][4][4];
    #pragma unroll
    for (int i = 0; i < 4; i++)
        #pragma unroll
        for (int j = 0; j < 4; j++)
            #pragma unroll
            for (int r = 0; r < 4; r++) acc[i][j][r] = 0.f;

    const int arowp = t >> 2, achp = t & 3;

    auto stage = [&](int ktile, int s) {
        const uint32_t ab = sb + s * G_STG;
        #pragma unroll
        for (int p = 0; p < 2; p++) {
            const int row = arowp + p * 64;
            CP16(ab + row * 80 + achp * 16,
                 (const char*)(Ab + (size_t)row * K + ktile * 32) + achp * 16);
        }
        const uint32_t bb = ab + 10240;
        const char* wsrc = (const char*)(Wtile0 + (size_t)ktile * 2048);
        CP16(bb + t * 16,         wsrc + t * 16);
        CP16(bb + (t + 256) * 16, wsrc + (t + 256) * 16);
    };

    const int army = ((lane >> 3) & 1) * 8 + (lane & 7);
    const int acol = ((lane >> 4) & 1) * 8;

    auto compute = [&](int s) {
        const uint32_t ab = sb + s * G_STG;
        const uint32_t* Bs = (const uint32_t*)(smc + s * G_STG + 10240);
        #pragma unroll
        for (int kt = 0; kt < 2; kt++) {
            uint4 af[4];
            #pragma unroll
            for (int mt = 0; mt < 4; mt++)
                ldm_x4(af[mt], ab + (uint32_t)((wy * 64 + mt * 16 + army) * 80
                                               + (kt * 16 + acol) * 2));
            uint2 bf[4];
            #pragma unroll
            for (int nt = 0; nt < 4; nt++)
                bf[nt] = *(const uint2*)&Bs[((kt * 16 + wx * 4 + nt) * 32 + lane) * 2];
            #pragma unroll
            for (int mt = 0; mt < 4; mt++)
                #pragma unroll
                for (int nt = 0; nt < 4; nt++)
                    mma_f16(acc[mt][nt], af[mt], bf[nt]);
        }
    };

    const int niter = K / 32;

    stage(0, 0);
    CP_COMMIT();
    for (int i = 0; i < niter; i++) {
        if (i + 1 < niter) {
            stage(i + 1, (i + 1) % 3);
            CP_COMMIT();
            CP_WAIT(1);
        } else {
            CP_WAIT(0);
        }
        __syncthreads();
        compute(i % 3);
    }

    // ---- epilogue ----
    __half* Cs = nullptr;
    int csub = 0;
    if (MODE == 3) {
        const int sel = bn / 768;
        Cs = (__half*)(sel == 0 ? Cv : (sel == 1 ? Cv2 : Cv3));
        csub = sel * 768;
    }

    const int rbase = bm + wy * 64 + (lane >> 2);
    const int cbase = bn + wx * 32 + (lane & 3) * 2;
    #pragma unroll
    for (int mt = 0; mt < 4; mt++) {
        #pragma unroll
        for (int nt = 0; nt < 4; nt++) {
            const int c = cbase + nt * 8;
            const float b0 = bias[c], b1 = bias[c + 1];
            const int r0 = rbase + mt * 16;
            const int r1 = r0 + 8;
            float v0 = acc[mt][nt][0] + b0;
            float v1 = acc[mt][nt][1] + b1;
            float v2 = acc[mt][nt][2] + b0;
            float v3 = acc[mt][nt][3] + b1;
            if (MODE == 1) {
                v0 = fmaxf(v0, 0.f); v1 = fmaxf(v1, 0.f);
                v2 = fmaxf(v2, 0.f); v3 = fmaxf(v3, 0.f);
            }
            if (MODE == 2) {
                const float2 q0 = *(const float2*)&res[(size_t)r0 * N + c];
                const float2 q1 = *(const float2*)&res[(size_t)r1 * N + c];
                float* C = (float*)Cv;
                *(float2*)&C[(size_t)r0 * N + c] = make_float2(v0 + q0.x, v1 + q0.y);
                *(float2*)&C[(size_t)r1 * N + c] = make_float2(v2 + q1.x, v3 + q1.y);
            } else if (MODE == 3) {
                const int cl = c - csub;
                *(uint32_t*)&Cs[(size_t)r0 * DM + cl] = pack_h2(v0, v1);
                *(uint32_t*)&Cs[(size_t)r1 * DM + cl] = pack_h2(v2, v3);
            } else {
                __half* C = (__half*)Cv;
                *(uint32_t*)&C[(size_t)r0 * N + c] = pack_h2(v0, v1);
                *(uint32_t*)&C[(size_t)r1 * N + c] = pack_h2(v2, v3);
            }
        }
    }
}

// =================== fp16 flash attention: cp.async + ldmatrix =============
// CTA: 128 queries (one (b,h)); 8 warps x 16 queries; BN=64 keys/iter.
// K,V row-major in smem (144B row stride), frags via ldmatrix / ldmatrix.trans.
// 3-stage ring, 1 sync/iter, register-resident P, log2-domain softmax.
#define A_STG   18688                 // K 9216 + V 9216 + mask 256
#define A_DSMEM (3 * A_STG)
#define SCL2    0.1803368801f         // 0.125 * log2(e)

__global__ void __launch_bounds__(256, 2)
attn_mma(const __half* __restrict__ Qh, const __half* __restrict__ Kh,
         const __half* __restrict__ Vh, const int* __restrict__ mask,
         __half* __restrict__ Oh) {
    extern __shared__ char smc[];
    const uint32_t sb = (uint32_t)__cvta_generic_to_shared(smc);

    const int t = threadIdx.x, lane = t & 31, wid = t >> 5;
    const int q0 = blockIdx.x * 128;
    const int h  = blockIdx.y, b = blockIdx.z;
    const size_t base = (size_t)b * S_LEN * DM + (size_t)h * DK;

    // ---- persistent Q A-fragments (16 queries per warp) ----
    const int qrow = q0 + wid * 16 + (lane >> 2);
    uint4 aq[4];
    #pragma unroll
    for (int kt = 0; kt < 4; kt++) {
        const __half* qp = Qh + base + (size_t)qrow * DM + kt * 16 + (lane & 3) * 2;
        aq[kt].x = *(const uint32_t*)qp;
        aq[kt].y = *(const uint32_t*)(qp + (size_t)8 * DM);
        aq[kt].z = *(const uint32_t*)(qp + 8);
        aq[kt].w = *(const uint32_t*)(qp + (size_t)8 * DM + 8);
    }

    float m0 = -INFINITY, m1 = -INFINITY, l0 = 0.f, l1 = 0.f;
    float o[8][4];
    #pragma unroll
    for (int i = 0; i < 8; i++)
        #pragma unroll
        for (int j = 0; j < 4; j++) o[i][j] = 0.f;

    const int srow = t >> 3, sch = t & 7;

    auto stage = [&](int ks0, int s) {
        const uint32_t kb = sb + s * A_STG;
        #pragma unroll
        for (int p = 0; p < 2; p++) {
            const int row = srow + p * 32;
            CP16(kb + row * 144 + sch * 16,
                 (const char*)(Kh + base + (size_t)(ks0 + row) * DM) + sch * 16);
            CP16(kb + 9216 + row * 144 + sch * 16,
                 (const char*)(Vh + base + (size_t)(ks0 + row) * DM) + sch * 16);
        }
        if (t < 16)
            CP16(kb + 18432 + t * 16, (const char*)(mask + (size_t)b * S_LEN + ks0) + t * 16);
    };

    const int krow = ((lane >> 4) & 1) * 8 + (lane & 7);
    const int kcol = ((lane >> 3) & 1) * 8;
    const int vrow = ((lane >> 3) & 1) * 8 + (lane & 7);
    const int vcol = ((lane >> 4) & 1) * 8;

    stage(0, 0);
    CP_COMMIT();

    for (int i = 0; i < 64; i++) {
        if (i + 1 < 64) {
            stage((i + 1) * 64, (i + 1) % 3);
            CP_COMMIT();
            CP_WAIT(1);
        } else {
            CP_WAIT(0);
        }
        __syncthreads();
        const int s = i % 3;
        const uint32_t kb = sb + s * A_STG;
        const uint32_t vb = kb + 9216;
        const int* mk = (const int*)(smc + s * A_STG + 18432);

        // ---- S = Q K^T ----
        float sc[8][4];
        #pragma unroll
        for (int nt = 0; nt < 8; nt++)
            #pragma unroll
            for (int r = 0; r < 4; r++) sc[nt][r] = 0.f;
        #pragma unroll
        for (int kt = 0; kt < 4; kt++) {
            uint2 bf[8];
            #pragma unroll
            for (int kg = 0; kg < 4; kg++) {
                uint4 r4;
                ldm_x4(r4, kb + (uint32_t)((kg * 16 + krow) * 144 + (kt * 16 + kcol) * 2));
                bf[2 * kg]     = make_uint2(r4.x, r4.y);
                bf[2 * kg + 1] = make_uint2(r4.z, r4.w);
            }
            #pragma unroll
            for (int nt = 0; nt < 8; nt++)
                mma_f16(sc[nt], aq[kt], bf[nt]);
        }

        // ---- mask + log2-scale + in-register row max ----
        float mx0 = -INFINITY, mx1 = -INFINITY;
        #pragma unroll
        for (int nt = 0; nt < 8; nt++) {
            const int c = nt * 8 + (lane & 3) * 2;
            const int2 mm = *(const int2*)&mk[c];
            const bool ma = mm.x != 0, mb = mm.y != 0;
            sc[nt][0] = ma ? sc[nt][0] * SCL2 : -1e9f;
            sc[nt][1] = mb ? sc[nt][1] * SCL2 : -1e9f;
            sc[nt][2] = ma ? sc[nt][2] * SCL2 : -1e9f;
            sc[nt][3] = mb ? sc[nt][3] * SCL2 : -1e9f;
            mx0 = fmaxf(mx0, fmaxf(sc[nt][0], sc[nt][1]));
            mx1 = fmaxf(mx1, fmaxf(sc[nt][2], sc[nt][3]));
        }
        mx0 = fmaxf(mx0, __shfl_xor_sync(0xffffffffu, mx0, 1));
        mx0 = fmaxf(mx0, __shfl_xor_sync(0xffffffffu, mx0, 2));
        mx1 = fmaxf(mx1, __shfl_xor_sync(0xffffffffu, mx1, 1));
        mx1 = fmaxf(mx1, __shfl_xor_sync(0xffffffffu, mx1, 2));
        const float mn0 = fmaxf(m0, mx0);
        const float mn1 = fmaxf(m1, mx1);
        const float fac0 = fexp2(m0 - mn0);
        const float fac1 = fexp2(m1 - mn1);
        m0 = mn0; m1 = mn1;

        // ---- exp2 + in-register P fragments ----
        float sum0 = 0.f, sum1 = 0.f;
        uint4 pf[4];
        #pragma unroll
        for (int k2 = 0; k2 < 4; k2++) {
            const int ne = 2 * k2, no = 2 * k2 + 1;
            const float p00 = fexp2(sc[ne][0] - mn0);
            const float p01 = fexp2(sc[ne][1] - mn0);
            const float p02 = fexp2(sc[ne][2] - mn1);
            const float p03 = fexp2(sc[ne][3] - mn1);
            const float p10 = fexp2(sc[no][0] - mn0);
            const float p11 = fexp2(sc[no][1] - mn0);
            const float p12 = fexp2(sc[no][2] - mn1);
            const float p13 = fexp2(sc[no][3] - mn1);
            sum0 += p00 + p01 + p10 + p11;
            sum1 += p02 + p03 + p12 + p13;
            pf[k2].x = pack_h2(p00, p01);
            pf[k2].y = pack_h2(p02, p03);
            pf[k2].z = pack_h2(p10, p11);
            pf[k2].w = pack_h2(p12, p13);
        }
        l0 = l0 * fac0 + sum0;
        l1 = l1 * fac1 + sum1;
        #pragma unroll
        for (int nt = 0; nt < 8; nt++) {
            o[nt][0] *= fac0; o[nt][1] *= fac0;
            o[nt][2] *= fac1; o[nt][3] *= fac1;
        }

        // ---- O += P V  (V frags via ldmatrix.trans) ----
        #pragma unroll
        for (int kt2 = 0; kt2 < 4; kt2++) {
            #pragma unroll
            for (int dp = 0; dp < 4; dp++) {
                uint4 r4;
                ldm_x4t(r4, vb + (uint32_t)((kt2 * 16 + vrow) * 144 + (dp * 16 + vcol) * 2));
                mma_f16(o[2 * dp],     pf[kt2], make_uint2(r4.x, r4.y));
                mma_f16(o[2 * dp + 1], pf[kt2], make_uint2(r4.z, r4.w));
            }
        }
    }

    // ---- finalize (quad-sum l, fully warp-local) ----
    l0 += __shfl_xor_sync(0xffffffffu, l0, 1);
    l0 += __shfl_xor_sync(0xffffffffu, l0, 2);
    l1 += __shfl_xor_sync(0xffffffffu, l1, 1);
    l1 += __shfl_xor_sync(0xffffffffu, l1, 2);
    const float inv0 = 1.f / l0;
    const float inv1 = 1.f / l1;

    #pragma unroll
    for (int nt = 0; nt < 8; nt++) {
        const int c = nt * 8 + (lane & 3) * 2;
        *(uint32_t*)&Oh[base + (size_t)qrow * DM + c] =
            pack_h2(o[nt][0] * inv0, o[nt][1] * inv0);
        *(uint32_t*)&Oh[base + (size_t)(qrow + 8) * DM + c] =
            pack_h2(o[nt][2] * inv1, o[nt][3] * inv1);
    }
}

// ---------------------------------------------------------------------------
extern "C" void kernel_launch(void* const* d_in, const int* in_sizes, int n_in,
                              void* d_out, int out_size) {
    const float* x      = (const float*)d_in[0];
    const int*   mask   = (const int*)  d_in[1];
    const float* wq     = (const float*)d_in[2];
    const float* bq     = (const float*)d_in[3];
    const float* wk     = (const float*)d_in[4];
    const float* bk     = (const float*)d_in[5];
    const float* wv     = (const float*)d_in[6];
    const float* bv     = (const float*)d_in[7];
    const float* wo     = (const float*)d_in[8];
    const float* bo     = (const float*)d_in[9];
    const float* w1     = (const float*)d_in[10];
    const float* b1     = (const float*)d_in[11];
    const float* w2     = (const float*)d_in[12];
    const float* b2     = (const float*)d_in[13];
    const float* alpha1 = (const float*)d_in[14];
    const float* beta1  = (const float*)d_in[15];
    const float* alpha2 = (const float*)d_in[16];
    const float* beta2  = (const float*)d_in[17];
    float* out = (float*)d_out;

    __half *h, *q, *k, *v, *ctx, *ff;
    float *x2, *bqkv;
    uint32_t *wqkvf, *wof, *w1f, *w2f;
    cudaGetSymbolAddress((void**)&h,     g_h);
    cudaGetSymbolAddress((void**)&q,     g_q);
    cudaGetSymbolAddress((void**)&k,     g_k);
    cudaGetSymbolAddress((void**)&v,     g_v);
    cudaGetSymbolAddress((void**)&ctx,   g_ctx);
    cudaGetSymbolAddress((void**)&x2,    g_x2);
    cudaGetSymbolAddress((void**)&ff,    g_ff);
    cudaGetSymbolAddress((void**)&bqkv,  g_bqkv);
    cudaGetSymbolAddress((void**)&wqkvf, g_wqkvf);
    cudaGetSymbolAddress((void**)&wof,   g_wof);
    cudaGetSymbolAddress((void**)&w1f,   g_w1f);
    cudaGetSymbolAddress((void**)&w2f,   g_w2f);

    cudaFuncSetAttribute(gemm_mma<0>, cudaFuncAttributeMaxDynamicSharedMemorySize, G_DSMEM);
    cudaFuncSetAttribute(gemm_mma<1>, cudaFuncAttributeMaxDynamicSharedMemorySize, G_DSMEM);
    cudaFuncSetAttribute(gemm_mma<2>, cudaFuncAttributeMaxDynamicSharedMemorySize, G_DSMEM);
    cudaFuncSetAttribute(gemm_mma<3>, cudaFuncAttributeMaxDynamicSharedMemorySize, G_DSMEM);
    cudaFuncSetAttribute(attn_mma,    cudaFuncAttributeMaxDynamicSharedMemorySize, A_DSMEM);

    // 0. weight prep (one fused launch) + bias concat
    prep_all<<<13824, 256>>>(wq, wk, wv, wo, w1, w2);
    cat_bias<<<9, 256>>>(bq, bk, bv, bqkv);

    const dim3 g_qkvg(QS / 128, NTOK / 128);   // (18, 64) fused qkv
    const dim3 g_n768(DM / 128, NTOK / 128);   // (6, 64)
    const dim3 g_ff1(DFF / 128, NTOK / 128);   // (24, 64)
    const dim3 attn_grid(S_LEN / 128, NH, BATCH);

    // 1. h = norm1(x)  (half out, warp-per-row)
    norm_kernel<<<NTOK / 8, 256>>>(x, h, alpha1, beta1);
    // 2. fused qkv projection -> separate q/k/v buffers (stride 768)
    gemm_mma<3><<<g_qkvg, 256, G_DSMEM>>>(h, wqkvf, bqkv, nullptr, q, k, v, NTOK, QS, DM);
    // 3. attention -> ctx
    attn_mma<<<attn_grid, 256, A_DSMEM>>>(q, k, v, mask, ctx);
    // 4. x2 = x + ctx @ wo^T + bo  (f32 out)
    gemm_mma<2><<<g_n768, 256, G_DSMEM>>>(ctx, wof, bo, x, x2, nullptr, nullptr, NTOK, DM, DM);
    // 5. h = norm2(x2) (half out)
    norm_kernel<<<NTOK / 8, 256>>>(x2, h, alpha2, beta2);
    // 6. ff = relu(h @ w1^T + b1)  (half out)
    gemm_mma<1><<<g_ff1, 256, G_DSMEM>>>(h, w1f, b1, nullptr, ff, nullptr, nullptr, NTOK, DFF, DM);
    // 7. out = x2 + ff @ w2^T + b2 (f32 out)
    gemm_mma<2><<<g_n768, 256, G_DSMEM>>>(ff, w2f, b2, x2, out, nullptr, nullptr, NTOK, DM, DFF);
}